// round 2
// baseline (speedup 1.0000x reference)
#include <cuda_runtime.h>

#define EPSV 1e-6f

typedef unsigned long long u64;

__device__ __forceinline__ u64 pack2(float x, float y){
    u64 r; asm("mov.b64 %0, {%1, %2};" : "=l"(r) : "f"(x), "f"(y)); return r;
}
__device__ __forceinline__ u64 ffma2(u64 a, u64 b, u64 c){
    u64 d; asm("fma.rn.f32x2 %0, %1, %2, %3;" : "=l"(d) : "l"(a), "l"(b), "l"(c)); return d;
}
__device__ __forceinline__ float2 unpack2(u64 a){
    float2 f; asm("mov.b64 {%0, %1}, %2;" : "=f"(f.x), "=f"(f.y) : "l"(a)); return f;
}

#define BB 8
#define HH 256
#define WW 256
#define CC 64
#define HID 128
#define OC1 256
#define NPIX (BB*HH*WW)

// Scratch (static __device__ globals per harness rules)
__device__ float g_t1[(size_t)NPIX * OC1];   // 512 MB: pw1 output
__device__ float g_y [(size_t)NPIX * HID];   // 256 MB: gated dw output
__device__ float g_x2[(size_t)NPIX * CC];    // 128 MB: stage-1 residual output
__device__ float g_part[BB * 1024 * HID];    // GAP partials per block
__device__ float g_attn[BB * HID];           // channel attention

// ---------------------------------------------------------------------------
// K1: LayerNorm1 + pw1 (64 -> 256)
// ---------------------------------------------------------------------------
__global__ void k1_ln_pw1(const float* __restrict__ x, const float* __restrict__ g1,
                          const float* __restrict__ b1, const float* __restrict__ W,
                          const float* __restrict__ bias)
{
    extern __shared__ float sm[];
    float* sW  = sm;                 // 64*256
    float* sB  = sm + 64*256;        // 256
    float* sG  = sB + 256;           // 64
    float* sBe = sG + 64;            // 64
    int tid = threadIdx.x;
    for (int i = tid; i < 64*256; i += 256) sW[i] = W[i];
    sB[tid] = bias[tid];
    if (tid < 64) { sG[tid] = g1[tid]; sBe[tid] = b1[tid]; }
    __syncthreads();

    size_t p = (size_t)blockIdx.x * 256 + tid;
    const float4* xp = (const float4*)(x + p * 64);
    float4 xv[16];
    #pragma unroll
    for (int q = 0; q < 16; q++) xv[q] = xp[q];
    float s = 0.f, ss = 0.f;
    #pragma unroll
    for (int q = 0; q < 16; q++){
        float4 v = xv[q];
        s += v.x + v.y + v.z + v.w;
        ss = fmaf(v.x,v.x, fmaf(v.y,v.y, fmaf(v.z,v.z, fmaf(v.w,v.w, ss))));
    }
    float mean = s * (1.f/64.f);
    float var  = fmaf(-mean, mean, ss * (1.f/64.f));
    float rstd = rsqrtf(var + EPSV);
    float ln[64];
    #pragma unroll
    for (int q = 0; q < 16; q++){
        float4 v = xv[q];
        ln[4*q+0] = fmaf((v.x-mean)*rstd, sG[4*q+0], sBe[4*q+0]);
        ln[4*q+1] = fmaf((v.y-mean)*rstd, sG[4*q+1], sBe[4*q+1]);
        ln[4*q+2] = fmaf((v.z-mean)*rstd, sG[4*q+2], sBe[4*q+2]);
        ln[4*q+3] = fmaf((v.w-mean)*rstd, sG[4*q+3], sBe[4*q+3]);
    }
    float* outp = g_t1 + p * 256;
    #pragma unroll 1
    for (int oc0 = 0; oc0 < 256; oc0 += 32){
        u64 acc[16];
        const u64* bb = (const u64*)(sB + oc0);
        #pragma unroll
        for (int j = 0; j < 16; j++) acc[j] = bb[j];
        #pragma unroll
        for (int k = 0; k < 64; k++){
            u64 a = pack2(ln[k], ln[k]);
            const ulonglong2* wr = (const ulonglong2*)(sW + k*256 + oc0);
            #pragma unroll
            for (int q = 0; q < 8; q++){
                ulonglong2 w = wr[q];
                acc[2*q]   = ffma2(a, w.x, acc[2*q]);
                acc[2*q+1] = ffma2(a, w.y, acc[2*q+1]);
            }
        }
        float4* op = (float4*)(outp + oc0);
        #pragma unroll
        for (int q = 0; q < 8; q++){
            float2 a = unpack2(acc[2*q]);
            float2 b = unpack2(acc[2*q+1]);
            op[q] = make_float4(a.x, a.y, b.x, b.y);
        }
    }
}

// ---------------------------------------------------------------------------
// K2: depthwise 3x3 (SAME) + SimpleGate + GAP partials
// thread = channel pair (c, c+128); block = 64-pixel row segment
// ---------------------------------------------------------------------------
__global__ void k2_dw_gate(const float* __restrict__ dww, const float* __restrict__ dwb)
{
    int blk = blockIdx.x;           // b*1024 + h*4 + wt
    int b   = blk >> 10;
    int rem = blk & 1023;
    int h   = rem >> 2;
    int w0  = (rem & 3) << 6;
    int c   = threadIdx.x;          // 0..127
    int c2  = c + 128;
    float wt0[9], wt1[9];
    #pragma unroll
    for (int i = 0; i < 9; i++){ wt0[i] = dww[i*256 + c]; wt1[i] = dww[i*256 + c2]; }
    float bc0 = dwb[c], bc1 = dwb[c2];

    const float* img = g_t1 + (size_t)b * HH * WW * 256;
    bool v0 = (h > 0), v2 = (h < HH-1);
    const float* r0 = img + (size_t)(h-1) * WW * 256;
    const float* r1 = img + (size_t)h     * WW * 256;
    const float* r2 = img + (size_t)(h+1) * WW * 256;

    float win0[9], win1[9];
    {
        int wm = w0 - 1;
        bool vm = (wm >= 0);
        win0[0] = (v0 && vm) ? r0[(size_t)wm*256 + c ] : 0.f;
        win0[3] =  vm        ? r1[(size_t)wm*256 + c ] : 0.f;
        win0[6] = (v2 && vm) ? r2[(size_t)wm*256 + c ] : 0.f;
        win1[0] = (v0 && vm) ? r0[(size_t)wm*256 + c2] : 0.f;
        win1[3] =  vm        ? r1[(size_t)wm*256 + c2] : 0.f;
        win1[6] = (v2 && vm) ? r2[(size_t)wm*256 + c2] : 0.f;
        win0[1] = v0 ? r0[(size_t)w0*256 + c ] : 0.f;
        win0[4] =      r1[(size_t)w0*256 + c ];
        win0[7] = v2 ? r2[(size_t)w0*256 + c ] : 0.f;
        win1[1] = v0 ? r0[(size_t)w0*256 + c2] : 0.f;
        win1[4] =      r1[(size_t)w0*256 + c2];
        win1[7] = v2 ? r2[(size_t)w0*256 + c2] : 0.f;
    }
    float* yrow = g_y + ((size_t)(b*HH + h) * WW) * 128;
    float gap = 0.f;
    for (int w = w0; w < w0 + 64; w++){
        int wp = w + 1;
        bool vp = (wp < WW);
        win0[2] = (v0 && vp) ? r0[(size_t)wp*256 + c ] : 0.f;
        win0[5] =  vp        ? r1[(size_t)wp*256 + c ] : 0.f;
        win0[8] = (v2 && vp) ? r2[(size_t)wp*256 + c ] : 0.f;
        win1[2] = (v0 && vp) ? r0[(size_t)wp*256 + c2] : 0.f;
        win1[5] =  vp        ? r1[(size_t)wp*256 + c2] : 0.f;
        win1[8] = (v2 && vp) ? r2[(size_t)wp*256 + c2] : 0.f;
        float a = bc0, bb = bc1;
        #pragma unroll
        for (int i = 0; i < 9; i++){ a = fmaf(win0[i], wt0[i], a); bb = fmaf(win1[i], wt1[i], bb); }
        float yv = a * bb;
        yrow[(size_t)w * 128 + c] = yv;
        gap += yv;
        #pragma unroll
        for (int r = 0; r < 3; r++){
            win0[r*3+0] = win0[r*3+1]; win0[r*3+1] = win0[r*3+2];
            win1[r*3+0] = win1[r*3+1]; win1[r*3+1] = win1[r*3+2];
        }
    }
    g_part[(size_t)blk * 128 + c] = gap;
}

// ---------------------------------------------------------------------------
// K3: GAP reduce + SCA (128 -> 128 on pooled means)
// ---------------------------------------------------------------------------
__global__ void k3_sca(const float* __restrict__ scaw, const float* __restrict__ scab)
{
    __shared__ float smn[128];
    int b = blockIdx.x, c = threadIdx.x;
    const float* p = g_part + (size_t)b * 1024 * 128 + c;
    float s = 0.f;
    #pragma unroll 8
    for (int i = 0; i < 1024; i++) s += p[(size_t)i * 128];
    smn[c] = s * (1.f / 65536.f);
    __syncthreads();
    float a = scab[c];
    #pragma unroll 8
    for (int k = 0; k < 128; k++) a = fmaf(smn[k], scaw[k*128 + c], a);
    g_attn[b*128 + c] = a;
}

// ---------------------------------------------------------------------------
// K4a: y*attn -> pw2 (128 -> 64) -> x2 = x + .*beta
// ---------------------------------------------------------------------------
__global__ void k4a_att_pw2(const float* __restrict__ x, const float* __restrict__ W2,
                            const float* __restrict__ b2, const float* __restrict__ beta)
{
    __shared__ __align__(16) float sW[128*64];
    __shared__ __align__(16) float sA[128];
    __shared__ __align__(16) float sB2[64];
    __shared__ __align__(16) float sBeta[64];
    int tid = threadIdx.x;
    int b = blockIdx.x >> 8;     // 256 blocks per image
    for (int i = tid; i < 128*64; i += 256) sW[i] = W2[i];
    if (tid < 128) sA[tid] = g_attn[b*128 + tid];
    if (tid < 64) { sB2[tid] = b2[tid]; sBeta[tid] = beta[tid]; }
    __syncthreads();
    size_t p = (size_t)blockIdx.x * 256 + tid;
    u64 acc[32];
    const u64* bb = (const u64*)sB2;
    #pragma unroll
    for (int j = 0; j < 32; j++) acc[j] = bb[j];
    const float4* yp = (const float4*)(g_y + p * 128);
    #pragma unroll 4
    for (int c4 = 0; c4 < 32; c4++){
        float4 yv = yp[c4];
        float va[4];
        va[0] = yv.x * sA[4*c4+0]; va[1] = yv.y * sA[4*c4+1];
        va[2] = yv.z * sA[4*c4+2]; va[3] = yv.w * sA[4*c4+3];
        #pragma unroll
        for (int r = 0; r < 4; r++){
            u64 a = pack2(va[r], va[r]);
            const ulonglong2* wr = (const ulonglong2*)(sW + (4*c4+r)*64);
            #pragma unroll
            for (int q = 0; q < 16; q++){
                ulonglong2 w = wr[q];
                acc[2*q]   = ffma2(a, w.x, acc[2*q]);
                acc[2*q+1] = ffma2(a, w.y, acc[2*q+1]);
            }
        }
    }
    const float4* xp = (const float4*)(x + p * 64);
    float4* op = (float4*)(g_x2 + p * 64);
    #pragma unroll
    for (int q = 0; q < 16; q++){
        float4 xv = xp[q];
        float2 a = unpack2(acc[2*q]);
        float2 c = unpack2(acc[2*q+1]);
        float4 o;
        o.x = fmaf(a.x, sBeta[4*q+0], xv.x);
        o.y = fmaf(a.y, sBeta[4*q+1], xv.y);
        o.z = fmaf(c.x, sBeta[4*q+2], xv.z);
        o.w = fmaf(c.y, sBeta[4*q+3], xv.w);
        op[q] = o;
    }
}

// ---------------------------------------------------------------------------
// K4b: LN2 -> pw3 (64 -> 256) -> gate -> pw4 (128 -> 64) -> out = x2 + .*gamma
// W3 stored interleaved as pairs (W3[k][j], W3[k][128+j]) so gate halves are adjacent
// ---------------------------------------------------------------------------
__global__ void k4b_ln_pw34(const float* __restrict__ W3, const float* __restrict__ b3,
                            const float* __restrict__ W4, const float* __restrict__ b4,
                            const float* __restrict__ g2, const float* __restrict__ bb2,
                            const float* __restrict__ gamma, float* __restrict__ out)
{
    extern __shared__ float sm[];
    float* sW3 = sm;             // 16384 floats (interleaved pairs)
    float* sW4 = sm + 16384;     // 8192
    float* sB3 = sW4 + 8192;     // 256 (interleaved pairs)
    float* sB4 = sB3 + 256;      // 64
    float* sG  = sB4 + 64;       // 64
    float* sBe = sG + 64;        // 64
    float* sGa = sBe + 64;       // 64
    int tid = threadIdx.x;       // 128
    for (int i = tid; i < 64*256; i += 128){
        int k = i >> 8, t = i & 255, j = t >> 1, hh = t & 1;
        sW3[i] = W3[k*256 + hh*128 + j];
    }
    for (int i = tid; i < 128*64; i += 128) sW4[i] = W4[i];
    sB3[2*tid] = b3[tid]; sB3[2*tid+1] = b3[128+tid];
    if (tid < 64){ sB4[tid]=b4[tid]; sG[tid]=g2[tid]; sBe[tid]=bb2[tid]; sGa[tid]=gamma[tid]; }
    __syncthreads();

    size_t p = (size_t)blockIdx.x * 128 + tid;
    const float4* xp = (const float4*)(g_x2 + p * 64);
    float s = 0.f, ssum = 0.f;
    #pragma unroll
    for (int q = 0; q < 16; q++){
        float4 v = xp[q];
        s += v.x+v.y+v.z+v.w;
        ssum = fmaf(v.x,v.x,fmaf(v.y,v.y,fmaf(v.z,v.z,fmaf(v.w,v.w,ssum))));
    }
    float mean = s * (1.f/64.f);
    float var  = fmaf(-mean, mean, ssum * (1.f/64.f));
    float rstd = rsqrtf(var + EPSV);
    float ln[64];
    #pragma unroll
    for (int q = 0; q < 16; q++){
        float4 v = xp[q];   // L1 re-hit
        ln[4*q+0] = fmaf((v.x-mean)*rstd, sG[4*q+0], sBe[4*q+0]);
        ln[4*q+1] = fmaf((v.y-mean)*rstd, sG[4*q+1], sBe[4*q+1]);
        ln[4*q+2] = fmaf((v.z-mean)*rstd, sG[4*q+2], sBe[4*q+2]);
        ln[4*q+3] = fmaf((v.w-mean)*rstd, sG[4*q+3], sBe[4*q+3]);
    }
    u64 acc[32];
    const u64* b4p = (const u64*)sB4;
    #pragma unroll
    for (int j = 0; j < 32; j++) acc[j] = b4p[j];
    const u64* b3p = (const u64*)sB3;
    #pragma unroll 1
    for (int jc = 0; jc < 16; jc++){
        u64 t3[8];
        #pragma unroll
        for (int ji = 0; ji < 8; ji++) t3[ji] = b3p[jc*8 + ji];
        #pragma unroll
        for (int k = 0; k < 64; k++){
            u64 a = pack2(ln[k], ln[k]);
            const ulonglong2* wr = (const ulonglong2*)(sW3 + k*256 + jc*16);
            #pragma unroll
            for (int q = 0; q < 4; q++){
                ulonglong2 w = wr[q];
                t3[2*q]   = ffma2(a, w.x, t3[2*q]);
                t3[2*q+1] = ffma2(a, w.y, t3[2*q+1]);
            }
        }
        #pragma unroll
        for (int ji = 0; ji < 8; ji++){
            float2 t = unpack2(t3[ji]);
            float gv = t.x * t.y;                 // SimpleGate
            u64 gg = pack2(gv, gv);
            const ulonglong2* wr = (const ulonglong2*)(sW4 + (jc*8 + ji)*64);
            #pragma unroll
            for (int q = 0; q < 16; q++){
                ulonglong2 w = wr[q];
                acc[2*q]   = ffma2(gg, w.x, acc[2*q]);
                acc[2*q+1] = ffma2(gg, w.y, acc[2*q+1]);
            }
        }
    }
    float4* op = (float4*)(out + p*64);
    #pragma unroll
    for (int q = 0; q < 16; q++){
        float4 xv = xp[q];
        float2 a = unpack2(acc[2*q]);
        float2 c = unpack2(acc[2*q+1]);
        float4 o;
        o.x = fmaf(a.x, sGa[4*q+0], xv.x);
        o.y = fmaf(a.y, sGa[4*q+1], xv.y);
        o.z = fmaf(c.x, sGa[4*q+2], xv.z);
        o.w = fmaf(c.y, sGa[4*q+3], xv.w);
        op[q] = o;
    }
}

// ---------------------------------------------------------------------------
extern "C" void kernel_launch(void* const* d_in, const int* in_sizes, int n_in,
                              void* d_out, int out_size)
{
    const float* x    = (const float*)d_in[0];
    const float* ln1g = (const float*)d_in[1];
    const float* ln1b = (const float*)d_in[2];
    const float* pw1w = (const float*)d_in[3];
    const float* pw1b = (const float*)d_in[4];
    const float* dww  = (const float*)d_in[5];
    const float* dwb  = (const float*)d_in[6];
    const float* scaw = (const float*)d_in[7];
    const float* scab = (const float*)d_in[8];
    const float* pw2w = (const float*)d_in[9];
    const float* pw2b = (const float*)d_in[10];
    const float* beta = (const float*)d_in[11];
    const float* ln2g = (const float*)d_in[12];
    const float* ln2b = (const float*)d_in[13];
    const float* pw3w = (const float*)d_in[14];
    const float* pw3b = (const float*)d_in[15];
    const float* pw4w = (const float*)d_in[16];
    const float* pw4b = (const float*)d_in[17];
    const float* gam  = (const float*)d_in[18];
    float* out = (float*)d_out;

    int smem1  = (64*256 + 256 + 64 + 64) * 4;                       // 67072
    int smem4b = (16384 + 8192 + 256 + 64 + 64 + 64 + 64) * 4;       // 100352
    cudaFuncSetAttribute(k1_ln_pw1,  cudaFuncAttributeMaxDynamicSharedMemorySize, smem1);
    cudaFuncSetAttribute(k4b_ln_pw34, cudaFuncAttributeMaxDynamicSharedMemorySize, smem4b);

    k1_ln_pw1 <<<NPIX/256, 256, smem1>>>(x, ln1g, ln1b, pw1w, pw1b);
    k2_dw_gate<<<BB*1024, 128>>>(dww, dwb);
    k3_sca    <<<BB, 128>>>(scaw, scab);
    k4a_att_pw2<<<NPIX/256, 256>>>(x, pw2w, pw2b, beta);
    k4b_ln_pw34<<<NPIX/128, 128, smem4b>>>(pw3w, pw3b, pw4w, pw4b, ln2g, ln2b, gam, out);
}